// round 16
// baseline (speedup 1.0000x reference)
#include <cuda_runtime.h>
#include <cuda_fp16.h>
#include <math.h>
#include <stdint.h>

// Problem constants
#define T_DIM 2048
#define B_DIM 2
#define E_DIM 1024
#define H_DIM 16
#define DH    64
#define MROWS (T_DIM * B_DIM)   // 4096
#define NELEM (MROWS * E_DIM)   // 4194304

// Scratch (device globals — no allocation allowed). All fp16.
__device__ __half gX[NELEM];                // input X, fp16
__device__ __half gW[NELEM];                // Wq,Wk,Wv,Wo fp16 (1M each)
__device__ __half gQ[NELEM], gK[NELEM], gV[NELEM];
__device__ __half gA[NELEM];                // attn output, fp16

// ===========================================================================
// Helpers
// ===========================================================================
__device__ __forceinline__ uint32_t smem_u32(const void* p) {
    uint32_t a;
    asm("{ .reg .u64 t; cvta.to.shared.u64 t, %1; cvt.u32.u64 %0, t; }" : "=r"(a) : "l"(p));
    return a;
}

#define LDSM4(R0, R1, R2, R3, ADDR) \
    asm volatile("ldmatrix.sync.aligned.m8n8.x4.shared.b16 {%0,%1,%2,%3}, [%4];" \
                 : "=r"(R0), "=r"(R1), "=r"(R2), "=r"(R3) : "r"(ADDR))

#define LDSM4T(R0, R1, R2, R3, ADDR) \
    asm volatile("ldmatrix.sync.aligned.m8n8.x4.trans.shared.b16 {%0,%1,%2,%3}, [%4];" \
                 : "=r"(R0), "=r"(R1), "=r"(R2), "=r"(R3) : "r"(ADDR))

#define MMA_F16(D, A, B0, B1) \
    asm volatile("mma.sync.aligned.m16n8k16.row.col.f32.f16.f16.f32 " \
                 "{%0,%1,%2,%3}, {%4,%5,%6,%7}, {%8,%9}, {%0,%1,%2,%3};" \
                 : "+f"((D)[0]), "+f"((D)[1]), "+f"((D)[2]), "+f"((D)[3]) \
                 : "r"((A)[0]), "r"((A)[1]), "r"((A)[2]), "r"((A)[3]), "r"(B0), "r"(B1))

#define CP_ASYNC16(DST, SRC) \
    asm volatile("cp.async.cg.shared.global [%0], [%1], 16;" :: "r"(DST), "l"(SRC) : "memory")
#define CP_COMMIT() asm volatile("cp.async.commit_group;" ::: "memory")
#define CP_WAIT(N)  asm volatile("cp.async.wait_group %0;" :: "n"(N) : "memory")

__device__ __forceinline__ uint32_t pack_h2(float a, float b) {
    __half2 h;
    h.x = __float2half_rn(a); h.y = __float2half_rn(b);
    return *(uint32_t*)&h;
}

// fast exp2 on FMA pipe (input already in log2 domain)
__device__ __forceinline__ float fast_exp2(float y) {
    y = fmaxf(y, -126.0f);
    int   e = __float2int_rn(y);
    float f = y - (float)e;
    float p = 1.33336e-3f;
    p = fmaf(p, f, 9.61812e-3f);
    p = fmaf(p, f, 5.55041e-2f);
    p = fmaf(p, f, 2.402265e-1f);
    p = fmaf(p, f, 6.931472e-1f);
    p = fmaf(p, f, 1.0f);
    return __int_as_float((e + 127) << 23) * p;
}

// exp2 on the MUFU pipe (idle in flash) — balances FMA-pipe pressure
__device__ __forceinline__ float mufu_exp2(float y) {
    float r;
    asm("ex2.approx.f32 %0, %1;" : "=f"(r) : "f"(y));
    return r;
}

// ===========================================================================
// Convert: X, Wq, Wk, Wv -> fp16 (Wo converted inside the flash launch).
// ===========================================================================
__global__ void __launch_bounds__(256)
convert_kernel(const float* __restrict__ X,
               const float* __restrict__ Wq, const float* __restrict__ Wk,
               const float* __restrict__ Wv)
{
    int gid = blockIdx.x * 256 + threadIdx.x;     // 0 .. 458751
    const float4* src;
    __half* dst;
    int off4;                                      // base offset in float4 units
    if (gid < 262144) {
        src = (const float4*)X; dst = gX; off4 = gid * 4;
    } else {
        int j = gid - 262144;
        int r = j >> 16;                           // 0..2 -> Wq,Wk,Wv
        off4 = (j & 0xFFFF) * 4;
        src = (r == 0) ? (const float4*)Wq : (r == 1) ? (const float4*)Wk : (const float4*)Wv;
        dst = gW + ((size_t)r << 20);
    }
#pragma unroll
    for (int t = 0; t < 4; ++t) {
        float4 v = src[off4 + t];
        *(uint2*)(dst + (size_t)(off4 + t) * 4) =
            make_uint2(pack_h2(v.x, v.y), pack_h2(v.z, v.w));
    }
}

// ===========================================================================
// GEMM: C = (A @ W^T + bias) * alpha, single fp16 term.  (R12/13 config —
// measured optimum: 256 thr / warp 64x32 / BK=64 / 3-stage / 2 CTAs/SM.)
// MODE 0: f32 out.  MODE 1: fp16 out.
// ===========================================================================
#define GPITCH 72                           // 64 halfs + 8 pad (conflict-free ldmatrix)
#define GARR_E (128 * GPITCH)               // 9216 elems per array
#define GSTAGE_E (2 * GARR_E)               // A + B = 18432 elems
#define GSMEM_BYTES (3 * GSTAGE_E * 2)      // 110592 B; 2 CTAs = 216 KB < 228 KB

__device__ __forceinline__ void gemm_produce(
    uint32_t smb, int stage,
    const __half* __restrict__ A, const __half* __restrict__ B,
    int row0, int col0, int k0, int tid)
{
#pragma unroll
    for (int i = 0; i < 8; ++i) {
        int id  = tid + i * 256;          // 0..2047
        int arr = id >> 10;               // 0:A 1:B
        int rid = (id >> 3) & 127;
        int cc  = id & 7;
        const __half* g = arr ? B : A;
        int grow = (arr ? col0 : row0) + rid;
        const __half* src = g + (size_t)grow * E_DIM + k0 + cc * 8;
        uint32_t dst = smb + (uint32_t)(stage * GSTAGE_E + arr * GARR_E + rid * GPITCH + cc * 8) * 2;
        CP_ASYNC16(dst, src);
    }
}

template <int MODE>
__device__ __forceinline__ void gemm_cp(
    const __half* __restrict__ A, const __half* __restrict__ B,
    const float* __restrict__ bias, float alpha,
    float* __restrict__ Cf, __half* __restrict__ Ch)
{
    extern __shared__ char dynsm[];
    const uint32_t smb = smem_u32(dynsm);
    const int tid  = threadIdx.x;
    const int lane = tid & 31;
    const int wid  = tid >> 5;
    const int wy   = wid >> 2;           // 0..1
    const int wx   = wid & 3;            // 0..3
    const int row0 = blockIdx.y * 128;
    const int col0 = blockIdx.x * 128;

    const int aOffE = (wy * 64 + (lane & 15)) * GPITCH + ((lane >> 4) & 1) * 8;
    const int bOffE = (wx * 32 + (lane & 7) + ((lane >> 4) & 1) * 8) * GPITCH + ((lane >> 3) & 1) * 8;

    float acc[4][4][4];
#pragma unroll
    for (int i = 0; i < 4; i++)
#pragma unroll
        for (int j = 0; j < 4; j++)
#pragma unroll
            for (int k = 0; k < 4; k++) acc[i][j][k] = 0.f;

    // prologue: chunks 0,1 into stages 0,1
    gemm_produce(smb, 0, A, B, row0, col0, 0, tid);
    CP_COMMIT();
    gemm_produce(smb, 1, A, B, row0, col0, 64, tid);
    CP_COMMIT();

    for (int c = 0; c < 16; ++c) {
        CP_WAIT(1);          // chunk c complete (one non-empty group per iter)
        __syncthreads();     // visible block-wide; prior readers of target stage done
        // wrap-around produce keeps groups non-empty; tail writes never re-read
        gemm_produce(smb, (c + 2) % 3, A, B, row0, col0, ((c + 2) & 15) * 64, tid);
        CP_COMMIT();

        const uint32_t stA = smb + (uint32_t)((c % 3) * GSTAGE_E) * 2;
        const uint32_t aHb = stA;
        const uint32_t bHb = stA + GARR_E * 2;

#pragma unroll
        for (int kb = 0; kb < 4; ++kb) {
            uint32_t bh[4][2];
#pragma unroll
            for (int np = 0; np < 2; ++np) {
                int boe = bOffE + np * 16 * GPITCH + kb * 16;
                LDSM4(bh[2 * np][0], bh[2 * np][1], bh[2 * np + 1][0], bh[2 * np + 1][1],
                      bHb + boe * 2);
            }
#pragma unroll
            for (int mf = 0; mf < 4; ++mf) {
                uint32_t ah[4];
                int aoe = aOffE + mf * 16 * GPITCH + kb * 16;
                LDSM4(ah[0], ah[1], ah[2], ah[3], aHb + aoe * 2);
                MMA_F16(acc[mf][0], ah, bh[0][0], bh[0][1]);
                MMA_F16(acc[mf][1], ah, bh[1][0], bh[1][1]);
                MMA_F16(acc[mf][2], ah, bh[2][0], bh[2][1]);
                MMA_F16(acc[mf][3], ah, bh[3][0], bh[3][1]);
            }
        }
    }
    CP_WAIT(0);   // drain wrap-around produces before exit

    // epilogue
#pragma unroll
    for (int mf = 0; mf < 4; ++mf) {
        int r = row0 + wy * 64 + mf * 16 + (lane >> 2);
#pragma unroll
        for (int nf = 0; nf < 4; ++nf) {
            int col = col0 + wx * 32 + nf * 8 + ((lane & 3) << 1);
            float b0 = bias[col], b1 = bias[col + 1];
            float v0 = (acc[mf][nf][0] + b0) * alpha;
            float v1 = (acc[mf][nf][1] + b1) * alpha;
            float v2 = (acc[mf][nf][2] + b0) * alpha;
            float v3 = (acc[mf][nf][3] + b1) * alpha;
            if (MODE == 0) {
                *(float2*)(Cf + (size_t)r * E_DIM + col)       = make_float2(v0, v1);
                *(float2*)(Cf + (size_t)(r + 8) * E_DIM + col) = make_float2(v2, v3);
            } else {
                *(uint32_t*)(Ch + (size_t)r * E_DIM + col)       = pack_h2(v0, v1);
                *(uint32_t*)(Ch + (size_t)(r + 8) * E_DIM + col) = pack_h2(v2, v3);
            }
        }
    }
}

__global__ void __launch_bounds__(256, 2)
qkv_kernel(const float* __restrict__ bq, const float* __restrict__ bk,
           const float* __restrict__ bv)
{
    const int z = blockIdx.z;
    const __half* Bh = gW + ((size_t)z << 20);
    // Q carries Dh^-0.5 * log2(e) so flash softmax works in exp2 domain
    if (z == 0)      gemm_cp<1>(gX, Bh, bq, 0.125f * 1.44269504f, nullptr, gQ);
    else if (z == 1) gemm_cp<1>(gX, Bh, bk, 1.0f, nullptr, gK);
    else             gemm_cp<1>(gX, Bh, bv, 1.0f, nullptr, gV);
}

__global__ void __launch_bounds__(256, 2)
oproj_kernel(const float* __restrict__ bo, float* __restrict__ out)
{
    gemm_cp<0>(gA, gW + ((size_t)3 << 20), bo, 1.0f, out, nullptr);
}

// ===========================================================================
// Flash attention (causal), fp16 Q/K/V, exp2-domain softmax.
// BR=128 (8 warps x m16), BC=64. 3-stage K/V pipeline; balanced q-tile pairs.
// Diagonal tiles: per-warp triangular clamping of S/softmax/PV column groups
// (CLAMPED template instantiation; full tiles stay branch-free).
// blockIdx.y==32 slice converts Wo -> fp16 in flash's shadow.
// ===========================================================================
#define FPITCH 72
#define FQ_E   (128 * FPITCH)              // 9216
#define FKV_E  (64 * FPITCH)               // 4608 per array
#define FSTAGE_E (2 * FKV_E)               // K + V per stage
#define FKV0_E FQ_E
#define FSMEM_BYTES ((FKV0_E + 3 * FSTAGE_E) * 2)   // 73728

__device__ __forceinline__ void flash_kv_produce(uint32_t smb, int stage, int j0,
                                                 int b, int colbase, int tid)
{
#pragma unroll
    for (int i = 0; i < 4; ++i) {
        int id  = tid + i * 256;          // 0..1023
        int arr = id >> 9;                // 0:K 1:V
        int rid = (id >> 3) & 63;
        int cc  = id & 7;
        const __half* g = arr ? gV : gK;
        const __half* src = g + ((size_t)(j0 + rid) * B_DIM + b) * E_DIM + colbase + cc * 8;
        uint32_t dst = smb + (uint32_t)(FKV0_E + stage * FSTAGE_E + arr * FKV_E + rid * FPITCH + cc * 8) * 2;
        CP_ASYNC16(dst, src);
    }
}

// One 128x64 S/softmax/PV tile. CLAMPED=false: branch-free full tile.
// CLAMPED=true: only S column groups np <= npmax are computed (the rest are
// fully causally masked -> P ~ 2^-126, dropped; error ~1e-36, negligible).
template <bool CLAMPED>
__device__ __forceinline__ void flash_tile(
    int npmax, int j0, uint32_t qB, uint32_t kB, uint32_t vB,
    int qOffE, int kOffE, int vOffE, int rg0, int lane,
    float (&s_m)[2], float (&s_l)[2], float (&o)[8][4])
{
    const int nfmax = 2 * npmax + 1;

    // ---- S = Q @ K^T (single term, log2-domain scores) ----
    float s[8][4];
#pragma unroll
    for (int i = 0; i < 8; i++)
#pragma unroll
        for (int j = 0; j < 4; j++) s[i][j] = 0.f;

#pragma unroll
    for (int kb = 0; kb < 4; ++kb) {
        uint32_t a[4];
        LDSM4(a[0], a[1], a[2], a[3], qB + (qOffE + kb * 16) * 2);
#pragma unroll
        for (int np = 0; np < 4; ++np) {
            if (CLAMPED && np > npmax) continue;
            uint32_t kh[4];
            int boe = kOffE + np * 16 * FPITCH + kb * 16;
            LDSM4(kh[0], kh[1], kh[2], kh[3], kB + boe * 2);
            MMA_F16(s[2 * np],     a, kh[0], kh[1]);
            MMA_F16(s[2 * np + 1], a, kh[2], kh[3]);
        }
    }

    // ---- causal element mask (only diagonal tiles are ever masked) ----
    if (CLAMPED) {
#pragma unroll
        for (int nf = 0; nf < 8; ++nf) {
            if (nf > nfmax) continue;
            int j = j0 + nf * 8 + ((lane & 3) << 1);
            if (j     > rg0)     s[nf][0] = -1e9f;
            if (j + 1 > rg0)     s[nf][1] = -1e9f;
            if (j     > rg0 + 8) s[nf][2] = -1e9f;
            if (j + 1 > rg0 + 8) s[nf][3] = -1e9f;
        }
    }

    // ---- online softmax in exp2 domain ----
    float vmax[2];
#pragma unroll
    for (int half = 0; half < 2; ++half) {
        const int e0 = half * 2, e1 = half * 2 + 1;
        float m = -1e9f;
#pragma unroll
        for (int nf = 0; nf < 8; ++nf) {
            if (CLAMPED && nf > nfmax) continue;
            m = fmaxf(m, fmaxf(s[nf][e0], s[nf][e1]));
        }
        m = fmaxf(m, __shfl_xor_sync(0xffffffffu, m, 1));
        m = fmaxf(m, __shfl_xor_sync(0xffffffffu, m, 2));
        vmax[half] = m;
    }
    const bool noresc = __all_sync(0xffffffffu,
                                   vmax[0] <= s_m[0] && vmax[1] <= s_m[1]);
#pragma unroll
    for (int half = 0; half < 2; ++half) {
        const int e0 = half * 2, e1 = half * 2 + 1;
        const float mnew = noresc ? s_m[half] : fmaxf(s_m[half], vmax[half]);
        float rsum = 0.f;
#pragma unroll
        for (int nf = 0; nf < 8; ++nf) {
            if (CLAMPED && nf > nfmax) continue;
            float p0 = mufu_exp2(s[nf][e0] - mnew);
            float p1 = fast_exp2(s[nf][e1] - mnew);
            s[nf][e0] = p0; s[nf][e1] = p1;
            rsum += p0 + p1;
        }
        rsum += __shfl_xor_sync(0xffffffffu, rsum, 1);
        rsum += __shfl_xor_sync(0xffffffffu, rsum, 2);
        if (noresc) {
            s_l[half] += rsum;
        } else {
            float corr = fast_exp2(s_m[half] - mnew);
            s_l[half] = s_l[half] * corr + rsum;
            s_m[half] = mnew;
#pragma unroll
            for (int nf = 0; nf < 8; ++nf) {
                o[nf][e0] *= corr;
                o[nf][e1] *= corr;
            }
        }
    }

    // ---- O += P @ V (single term; kc indexes S column groups) ----
#pragma unroll
    for (int kc = 0; kc < 4; ++kc) {
        if (CLAMPED && kc > npmax) continue;
        uint32_t ph[4];
        ph[0] = pack_h2(s[2 * kc][0],     s[2 * kc][1]);
        ph[1] = pack_h2(s[2 * kc][2],     s[2 * kc][3]);
        ph[2] = pack_h2(s[2 * kc + 1][0], s[2 * kc + 1][1]);
        ph[3] = pack_h2(s[2 * kc + 1][2], s[2 * kc + 1][3]);
        uint32_t wh[4][4];
#pragma unroll
        for (int np = 0; np < 4; ++np) {
            int voe = vOffE + kc * 16 * FPITCH + np * 16;
            LDSM4T(wh[np][0], wh[np][1], wh[np][2], wh[np][3], vB + voe * 2);
        }
#pragma unroll
        for (int np = 0; np < 4; ++np) {
            MMA_F16(o[2 * np],     ph, wh[np][0], wh[np][1]);
            MMA_F16(o[2 * np + 1], ph, wh[np][2], wh[np][3]);
        }
    }
}

__device__ __forceinline__ void flash_one(int qt, uint32_t smb, int b, int colbase,
                                          int tid, int lane, int w,
                                          int qOffE, int kOffE, int vOffE)
{
    const int i0 = qt * 128;
    const int ktmax = 2 * qt + 1;         // >= 1 always

    // prologue: group0 = Q + kv0; group1 = kv1
#pragma unroll
    for (int i = 0; i < 4; ++i) {
        int id  = tid + i * 256;          // 0..1023
        int rid = id >> 3;
        int cc  = id & 7;
        const __half* src = gQ + ((size_t)(i0 + rid) * B_DIM + b) * E_DIM + colbase + cc * 8;
        uint32_t dst = smb + (uint32_t)(rid * FPITCH + cc * 8) * 2;
        CP_ASYNC16(dst, src);
    }
    flash_kv_produce(smb, 0, 0, b, colbase, tid);
    CP_COMMIT();
    flash_kv_produce(smb, 1, 64, b, colbase, tid);
    CP_COMMIT();

    float s_m[2] = {-1e9f, -1e9f};
    float s_l[2] = {0.f, 0.f};
    float o[8][4];
#pragma unroll
    for (int i = 0; i < 8; i++)
#pragma unroll
        for (int j = 0; j < 4; j++) o[i][j] = 0.f;

    const int rg0 = i0 + w * 16 + (lane >> 2);
    const uint32_t qB = smb;

    for (int kt = 0; kt <= ktmax; ++kt) {
        CP_WAIT(1);           // tile kt landed (one non-empty group per iter)
        __syncthreads();
        {   // wrap-around produce (clamped index; unread duplicates at tail)
            int ktn = (kt + 2 <= ktmax) ? (kt + 2) : ktmax;
            flash_kv_produce(smb, (kt + 2) % 3, ktn * 64, b, colbase, tid);
            CP_COMMIT();
        }

        const int j0 = kt * 64;
        const uint32_t stKV = smb + (uint32_t)(FKV0_E + (kt % 3) * FSTAGE_E) * 2;
        const uint32_t kB = stKV;
        const uint32_t vB = stKV + FKV_E * 2;

        if (kt >= ktmax - 1) {
            // diagonal region (the only masked tiles)
            if (kt == ktmax) {
                // j0 = i0+64: warps 0-3 fully masked (exact no-op); warps 4-7
                // need S col groups np <= w-4.
                if (w >= 4)
                    flash_tile<true>(w - 4, j0, qB, kB, vB,
                                     qOffE, kOffE, vOffE, rg0, lane, s_m, s_l, o);
            } else {
                // j0 = i0: warp w needs S col groups np <= min(3, w).
                flash_tile<true>(w < 3 ? w : 3, j0, qB, kB, vB,
                                 qOffE, kOffE, vOffE, rg0, lane, s_m, s_l, o);
            }
        } else {
            flash_tile<false>(3, j0, qB, kB, vB,
                              qOffE, kOffE, vOffE, rg0, lane, s_m, s_l, o);
        }
    }
    CP_WAIT(0);        // drain wrap-around produces (next call reuses stages)
    __syncthreads();   // smem reads done before caller refills Q region

    // ---- finalize: attn = o / l, stored as fp16 ----
    const float inv0 = 1.f / s_l[0];
    const float inv1 = 1.f / s_l[1];
#pragma unroll
    for (int nf = 0; nf < 8; ++nf) {
        int col = colbase + nf * 8 + ((lane & 3) << 1);
        size_t r0off = ((size_t)rg0 * B_DIM + b) * E_DIM + col;
        size_t r1off = ((size_t)(rg0 + 8) * B_DIM + b) * E_DIM + col;
        *(uint32_t*)(gA + r0off) = pack_h2(o[nf][0] * inv0, o[nf][1] * inv0);
        *(uint32_t*)(gA + r1off) = pack_h2(o[nf][2] * inv1, o[nf][3] * inv1);
    }
}

__global__ void __launch_bounds__(256)
flash_mma_kernel(const float* __restrict__ Wo)
{
    extern __shared__ char dynsm[];
    const uint32_t smb = smem_u32(dynsm);

    const int tid  = threadIdx.x;

    // ---- side slice: convert Wo -> fp16 in flash's shadow ----
    if (blockIdx.y == 32) {
        const float4* src = (const float4*)Wo;
        __half* dst = gW + ((size_t)3 << 20);
        const int base = blockIdx.x * 256 + tid;      // 0..2047
#pragma unroll 4
        for (int i = base; i < 262144; i += 2048) {
            float4 v = src[i];
            *(uint2*)(dst + (size_t)i * 4) =
                make_uint2(pack_h2(v.x, v.y), pack_h2(v.z, v.w));
        }
        return;
    }

    const int lane = tid & 31;
    const int w    = tid >> 5;
    const int pair = blockIdx.x;          // 0..7
    const int head = blockIdx.y;          // 0..31
    const int b    = head >> 4;
    const int h    = head & 15;
    const int colbase = h * DH;

    const int qOffE = (w * 16 + (lane & 15)) * FPITCH + ((lane >> 4) & 1) * 8;
    const int kOffE = ((lane & 7) + ((lane >> 4) & 1) * 8) * FPITCH + ((lane >> 3) & 1) * 8;
    const int vOffE = ((lane & 7) + ((lane >> 3) & 1) * 8) * FPITCH + ((lane >> 4) & 1) * 8;

    // balanced pair: (pair) and (15 - pair) -> 34 kv-tiles per CTA, uniform
    flash_one(pair,      smb, b, colbase, tid, lane, w, qOffE, kOffE, vOffE);
    flash_one(15 - pair, smb, b, colbase, tid, lane, w, qOffE, kOffE, vOffE);
}

// ===========================================================================
// kernel_launch
// Inputs: query, Wq, bq, Wk, bk, Wv, bv, Wo, bo, attn_mask (ignored: causal)
// ===========================================================================
extern "C" void kernel_launch(void* const* d_in, const int* in_sizes, int n_in,
                              void* d_out, int out_size)
{
    const float* query = (const float*)d_in[0];
    const float* Wq    = (const float*)d_in[1];
    const float* bq    = (const float*)d_in[2];
    const float* Wk    = (const float*)d_in[3];
    const float* bk    = (const float*)d_in[4];
    const float* Wv    = (const float*)d_in[5];
    const float* bv    = (const float*)d_in[6];
    const float* Wo    = (const float*)d_in[7];
    const float* bo    = (const float*)d_in[8];
    float* out = (float*)d_out;

    cudaFuncSetAttribute(qkv_kernel, cudaFuncAttributeMaxDynamicSharedMemorySize, GSMEM_BYTES);
    cudaFuncSetAttribute(oproj_kernel, cudaFuncAttributeMaxDynamicSharedMemorySize, GSMEM_BYTES);
    cudaFuncSetAttribute(flash_mma_kernel, cudaFuncAttributeMaxDynamicSharedMemorySize, FSMEM_BYTES);

    // X, Wq, Wk, Wv -> fp16 (Wo converted inside the flash launch)
    convert_kernel<<<1792, 256>>>(query, Wq, Wk, Wv);

    // QKV projections (all 1-term) -> fp16 q,k,v
    qkv_kernel<<<dim3(E_DIM / 128, MROWS / 128, 3), 256, GSMEM_BYTES>>>(bq, bk, bv);

    // causal flash attention: 8 balanced q-tile pairs x 32 heads,
    // + y==32 slice converts Wo in the flash shadow
    flash_mma_kernel<<<dim3(8, B_DIM * H_DIM + 1), 256, FSMEM_BYTES>>>(Wo);

    // output projection -> f32 out
    oproj_kernel<<<dim3(E_DIM / 128, MROWS / 128), 256, GSMEM_BYTES>>>(bo, out);
}

// round 17
// speedup vs baseline: 1.0166x; 1.0166x over previous
#include <cuda_runtime.h>
#include <cuda_fp16.h>
#include <math.h>
#include <stdint.h>

// Problem constants
#define T_DIM 2048
#define B_DIM 2
#define E_DIM 1024
#define H_DIM 16
#define DH    64
#define MROWS (T_DIM * B_DIM)   // 4096
#define NELEM (MROWS * E_DIM)   // 4194304

// Scratch (device globals — no allocation allowed). All fp16.
__device__ __half gX[NELEM];                // input X, fp16
__device__ __half gW[NELEM];                // Wq,Wk,Wv,Wo fp16 (1M each)
__device__ __half gQ[NELEM], gK[NELEM], gV[NELEM];
__device__ __half gA[NELEM];                // attn output, fp16

// ===========================================================================
// Helpers
// ===========================================================================
__device__ __forceinline__ uint32_t smem_u32(const void* p) {
    uint32_t a;
    asm("{ .reg .u64 t; cvta.to.shared.u64 t, %1; cvt.u32.u64 %0, t; }" : "=r"(a) : "l"(p));
    return a;
}

#define LDSM4(R0, R1, R2, R3, ADDR) \
    asm volatile("ldmatrix.sync.aligned.m8n8.x4.shared.b16 {%0,%1,%2,%3}, [%4];" \
                 : "=r"(R0), "=r"(R1), "=r"(R2), "=r"(R3) : "r"(ADDR))

#define LDSM4T(R0, R1, R2, R3, ADDR) \
    asm volatile("ldmatrix.sync.aligned.m8n8.x4.trans.shared.b16 {%0,%1,%2,%3}, [%4];" \
                 : "=r"(R0), "=r"(R1), "=r"(R2), "=r"(R3) : "r"(ADDR))

#define MMA_F16(D, A, B0, B1) \
    asm volatile("mma.sync.aligned.m16n8k16.row.col.f32.f16.f16.f32 " \
                 "{%0,%1,%2,%3}, {%4,%5,%6,%7}, {%8,%9}, {%0,%1,%2,%3};" \
                 : "+f"((D)[0]), "+f"((D)[1]), "+f"((D)[2]), "+f"((D)[3]) \
                 : "r"((A)[0]), "r"((A)[1]), "r"((A)[2]), "r"((A)[3]), "r"(B0), "r"(B1))

#define CP_ASYNC16(DST, SRC) \
    asm volatile("cp.async.cg.shared.global [%0], [%1], 16;" :: "r"(DST), "l"(SRC) : "memory")
#define CP_COMMIT() asm volatile("cp.async.commit_group;" ::: "memory")
#define CP_WAIT(N)  asm volatile("cp.async.wait_group %0;" :: "n"(N) : "memory")

__device__ __forceinline__ uint32_t pack_h2(float a, float b) {
    __half2 h;
    h.x = __float2half_rn(a); h.y = __float2half_rn(b);
    return *(uint32_t*)&h;
}

// fast exp2 on FMA pipe (input already in log2 domain)
__device__ __forceinline__ float fast_exp2(float y) {
    y = fmaxf(y, -126.0f);
    int   e = __float2int_rn(y);
    float f = y - (float)e;
    float p = 1.33336e-3f;
    p = fmaf(p, f, 9.61812e-3f);
    p = fmaf(p, f, 5.55041e-2f);
    p = fmaf(p, f, 2.402265e-1f);
    p = fmaf(p, f, 6.931472e-1f);
    p = fmaf(p, f, 1.0f);
    return __int_as_float((e + 127) << 23) * p;
}

// exp2 on the MUFU pipe (idle in flash) — balances FMA-pipe pressure
__device__ __forceinline__ float mufu_exp2(float y) {
    float r;
    asm("ex2.approx.f32 %0, %1;" : "=f"(r) : "f"(y));
    return r;
}

// ===========================================================================
// Convert: X, Wq, Wk, Wv -> fp16 (Wo converted inside the flash launch).
// ===========================================================================
__global__ void __launch_bounds__(256)
convert_kernel(const float* __restrict__ X,
               const float* __restrict__ Wq, const float* __restrict__ Wk,
               const float* __restrict__ Wv)
{
    int gid = blockIdx.x * 256 + threadIdx.x;     // 0 .. 458751
    const float4* src;
    __half* dst;
    int off4;                                      // base offset in float4 units
    if (gid < 262144) {
        src = (const float4*)X; dst = gX; off4 = gid * 4;
    } else {
        int j = gid - 262144;
        int r = j >> 16;                           // 0..2 -> Wq,Wk,Wv
        off4 = (j & 0xFFFF) * 4;
        src = (r == 0) ? (const float4*)Wq : (r == 1) ? (const float4*)Wk : (const float4*)Wv;
        dst = gW + ((size_t)r << 20);
    }
#pragma unroll
    for (int t = 0; t < 4; ++t) {
        float4 v = src[off4 + t];
        *(uint2*)(dst + (size_t)(off4 + t) * 4) =
            make_uint2(pack_h2(v.x, v.y), pack_h2(v.z, v.w));
    }
}

// ===========================================================================
// GEMM: C = (A @ W^T + bias) * alpha, single fp16 term.  (R12/13 config —
// measured optimum: 256 thr / warp 64x32 / BK=64 / 3-stage / 2 CTAs/SM.)
// MODE 0: f32 out.  MODE 1: fp16 out.
// ===========================================================================
#define GPITCH 72                           // 64 halfs + 8 pad (conflict-free ldmatrix)
#define GARR_E (128 * GPITCH)               // 9216 elems per array
#define GSTAGE_E (2 * GARR_E)               // A + B = 18432 elems
#define GSMEM_BYTES (3 * GSTAGE_E * 2)      // 110592 B; 2 CTAs = 216 KB < 228 KB

__device__ __forceinline__ void gemm_produce(
    uint32_t smb, int stage,
    const __half* __restrict__ A, const __half* __restrict__ B,
    int row0, int col0, int k0, int tid)
{
#pragma unroll
    for (int i = 0; i < 8; ++i) {
        int id  = tid + i * 256;          // 0..2047
        int arr = id >> 10;               // 0:A 1:B
        int rid = (id >> 3) & 127;
        int cc  = id & 7;
        const __half* g = arr ? B : A;
        int grow = (arr ? col0 : row0) + rid;
        const __half* src = g + (size_t)grow * E_DIM + k0 + cc * 8;
        uint32_t dst = smb + (uint32_t)(stage * GSTAGE_E + arr * GARR_E + rid * GPITCH + cc * 8) * 2;
        CP_ASYNC16(dst, src);
    }
}

template <int MODE>
__device__ __forceinline__ void gemm_cp(
    const __half* __restrict__ A, const __half* __restrict__ B,
    const float* __restrict__ bias, float alpha,
    float* __restrict__ Cf, __half* __restrict__ Ch)
{
    extern __shared__ char dynsm[];
    const uint32_t smb = smem_u32(dynsm);
    const int tid  = threadIdx.x;
    const int lane = tid & 31;
    const int wid  = tid >> 5;
    const int wy   = wid >> 2;           // 0..1
    const int wx   = wid & 3;            // 0..3
    const int row0 = blockIdx.y * 128;
    const int col0 = blockIdx.x * 128;

    const int aOffE = (wy * 64 + (lane & 15)) * GPITCH + ((lane >> 4) & 1) * 8;
    const int bOffE = (wx * 32 + (lane & 7) + ((lane >> 4) & 1) * 8) * GPITCH + ((lane >> 3) & 1) * 8;

    float acc[4][4][4];
#pragma unroll
    for (int i = 0; i < 4; i++)
#pragma unroll
        for (int j = 0; j < 4; j++)
#pragma unroll
            for (int k = 0; k < 4; k++) acc[i][j][k] = 0.f;

    // prologue: chunks 0,1 into stages 0,1
    gemm_produce(smb, 0, A, B, row0, col0, 0, tid);
    CP_COMMIT();
    gemm_produce(smb, 1, A, B, row0, col0, 64, tid);
    CP_COMMIT();

    for (int c = 0; c < 16; ++c) {
        CP_WAIT(1);          // chunk c complete (one non-empty group per iter)
        __syncthreads();     // visible block-wide; prior readers of target stage done
        // wrap-around produce keeps groups non-empty; tail writes never re-read
        gemm_produce(smb, (c + 2) % 3, A, B, row0, col0, ((c + 2) & 15) * 64, tid);
        CP_COMMIT();

        const uint32_t stA = smb + (uint32_t)((c % 3) * GSTAGE_E) * 2;
        const uint32_t aHb = stA;
        const uint32_t bHb = stA + GARR_E * 2;

#pragma unroll
        for (int kb = 0; kb < 4; ++kb) {
            uint32_t bh[4][2];
#pragma unroll
            for (int np = 0; np < 2; ++np) {
                int boe = bOffE + np * 16 * GPITCH + kb * 16;
                LDSM4(bh[2 * np][0], bh[2 * np][1], bh[2 * np + 1][0], bh[2 * np + 1][1],
                      bHb + boe * 2);
            }
#pragma unroll
            for (int mf = 0; mf < 4; ++mf) {
                uint32_t ah[4];
                int aoe = aOffE + mf * 16 * GPITCH + kb * 16;
                LDSM4(ah[0], ah[1], ah[2], ah[3], aHb + aoe * 2);
                MMA_F16(acc[mf][0], ah, bh[0][0], bh[0][1]);
                MMA_F16(acc[mf][1], ah, bh[1][0], bh[1][1]);
                MMA_F16(acc[mf][2], ah, bh[2][0], bh[2][1]);
                MMA_F16(acc[mf][3], ah, bh[3][0], bh[3][1]);
            }
        }
    }
    CP_WAIT(0);   // drain wrap-around produces before exit

    // epilogue
#pragma unroll
    for (int mf = 0; mf < 4; ++mf) {
        int r = row0 + wy * 64 + mf * 16 + (lane >> 2);
#pragma unroll
        for (int nf = 0; nf < 4; ++nf) {
            int col = col0 + wx * 32 + nf * 8 + ((lane & 3) << 1);
            float b0 = bias[col], b1 = bias[col + 1];
            float v0 = (acc[mf][nf][0] + b0) * alpha;
            float v1 = (acc[mf][nf][1] + b1) * alpha;
            float v2 = (acc[mf][nf][2] + b0) * alpha;
            float v3 = (acc[mf][nf][3] + b1) * alpha;
            if (MODE == 0) {
                *(float2*)(Cf + (size_t)r * E_DIM + col)       = make_float2(v0, v1);
                *(float2*)(Cf + (size_t)(r + 8) * E_DIM + col) = make_float2(v2, v3);
            } else {
                *(uint32_t*)(Ch + (size_t)r * E_DIM + col)       = pack_h2(v0, v1);
                *(uint32_t*)(Ch + (size_t)(r + 8) * E_DIM + col) = pack_h2(v2, v3);
            }
        }
    }
}

__global__ void __launch_bounds__(256, 2)
qkv_kernel(const float* __restrict__ bq, const float* __restrict__ bk,
           const float* __restrict__ bv)
{
    const int z = blockIdx.z;
    const __half* Bh = gW + ((size_t)z << 20);
    // Q carries Dh^-0.5 * log2(e) so flash softmax works in exp2 domain
    if (z == 0)      gemm_cp<1>(gX, Bh, bq, 0.125f * 1.44269504f, nullptr, gQ);
    else if (z == 1) gemm_cp<1>(gX, Bh, bk, 1.0f, nullptr, gK);
    else             gemm_cp<1>(gX, Bh, bv, 1.0f, nullptr, gV);
}

__global__ void __launch_bounds__(256, 2)
oproj_kernel(const float* __restrict__ bo, float* __restrict__ out)
{
    gemm_cp<0>(gA, gW + ((size_t)3 << 20), bo, 1.0f, out, nullptr);
}

// ===========================================================================
// Flash attention (causal), fp16 Q/K/V, exp2-domain softmax.
// BR=128 (8 warps x m16), BC=64. 3-stage K/V pipeline; balanced q-tile pairs.
// Warps 0-3 skip the fully-masked final diagonal tile (bit-exact skip).
// __launch_bounds__(256,2): cap regs at 128 so 2 CTAs/SM (single wave).
// blockIdx.y==32 slice converts Wo -> fp16 in flash's shadow.
// ===========================================================================
#define FPITCH 72
#define FQ_E   (128 * FPITCH)              // 9216
#define FKV_E  (64 * FPITCH)               // 4608 per array
#define FSTAGE_E (2 * FKV_E)               // K + V per stage
#define FKV0_E FQ_E
#define FSMEM_BYTES ((FKV0_E + 3 * FSTAGE_E) * 2)   // 73728

__device__ __forceinline__ void flash_kv_produce(uint32_t smb, int stage, int j0,
                                                 int b, int colbase, int tid)
{
#pragma unroll
    for (int i = 0; i < 4; ++i) {
        int id  = tid + i * 256;          // 0..1023
        int arr = id >> 9;                // 0:K 1:V
        int rid = (id >> 3) & 63;
        int cc  = id & 7;
        const __half* g = arr ? gV : gK;
        const __half* src = g + ((size_t)(j0 + rid) * B_DIM + b) * E_DIM + colbase + cc * 8;
        uint32_t dst = smb + (uint32_t)(FKV0_E + stage * FSTAGE_E + arr * FKV_E + rid * FPITCH + cc * 8) * 2;
        CP_ASYNC16(dst, src);
    }
}

__device__ __forceinline__ void flash_one(int qt, uint32_t smb, int b, int colbase,
                                          int tid, int lane, int w,
                                          int qOffE, int kOffE, int vOffE)
{
    const int i0 = qt * 128;
    const int ktmax = 2 * qt + 1;         // >= 1 always

    // prologue: group0 = Q + kv0; group1 = kv1
#pragma unroll
    for (int i = 0; i < 4; ++i) {
        int id  = tid + i * 256;          // 0..1023
        int rid = id >> 3;
        int cc  = id & 7;
        const __half* src = gQ + ((size_t)(i0 + rid) * B_DIM + b) * E_DIM + colbase + cc * 8;
        uint32_t dst = smb + (uint32_t)(rid * FPITCH + cc * 8) * 2;
        CP_ASYNC16(dst, src);
    }
    flash_kv_produce(smb, 0, 0, b, colbase, tid);
    CP_COMMIT();
    flash_kv_produce(smb, 1, 64, b, colbase, tid);
    CP_COMMIT();

    float s_m[2] = {-1e9f, -1e9f};
    float s_l[2] = {0.f, 0.f};
    float o[8][4];
#pragma unroll
    for (int i = 0; i < 8; i++)
#pragma unroll
        for (int j = 0; j < 4; j++) o[i][j] = 0.f;

    const int rg0 = i0 + w * 16 + (lane >> 2);
    const uint32_t qB = smb;

    for (int kt = 0; kt <= ktmax; ++kt) {
        CP_WAIT(1);           // tile kt landed (one non-empty group per iter)
        __syncthreads();
        {   // wrap-around produce (clamped index; unread duplicates at tail)
            int ktn = (kt + 2 <= ktmax) ? (kt + 2) : ktmax;
            flash_kv_produce(smb, (kt + 2) % 3, ktn * 64, b, colbase, tid);
            CP_COMMIT();
        }

        // Final diagonal tile (j0 = i0+64): warps 0-3 are entirely above the
        // diagonal -> S fully masked -> P == 0 -> exact no-op. Skip the body.
        // Warp-uniform branch; all barriers are outside this conditional.
        if (kt == ktmax && w < 4) continue;

        const int j0 = kt * 64;
        const uint32_t stKV = smb + (uint32_t)(FKV0_E + (kt % 3) * FSTAGE_E) * 2;
        const uint32_t kB = stKV;
        const uint32_t vB = stKV + FKV_E * 2;

        // ---- S = Q @ K^T (single term, log2-domain scores) ----
        float s[8][4];
#pragma unroll
        for (int i = 0; i < 8; i++)
#pragma unroll
            for (int j = 0; j < 4; j++) s[i][j] = 0.f;

#pragma unroll
        for (int kb = 0; kb < 4; ++kb) {
            uint32_t a[4];
            LDSM4(a[0], a[1], a[2], a[3], qB + (qOffE + kb * 16) * 2);
            uint32_t kh[4][4];
#pragma unroll
            for (int np = 0; np < 4; ++np) {
                int boe = kOffE + np * 16 * FPITCH + kb * 16;
                LDSM4(kh[np][0], kh[np][1], kh[np][2], kh[np][3], kB + boe * 2);
            }
#pragma unroll
            for (int np = 0; np < 4; ++np) {
                MMA_F16(s[2 * np],     a, kh[np][0], kh[np][1]);
                MMA_F16(s[2 * np + 1], a, kh[np][2], kh[np][3]);
            }
        }

        // ---- causal mask ----
        if (j0 + 63 > i0 + w * 16) {
#pragma unroll
            for (int nf = 0; nf < 8; ++nf) {
                int j = j0 + nf * 8 + ((lane & 3) << 1);
                if (j     > rg0)     s[nf][0] = -1e9f;
                if (j + 1 > rg0)     s[nf][1] = -1e9f;
                if (j     > rg0 + 8) s[nf][2] = -1e9f;
                if (j + 1 > rg0 + 8) s[nf][3] = -1e9f;
            }
        }

        // ---- online softmax in exp2 domain ----
        float vmax[2];
#pragma unroll
        for (int half = 0; half < 2; ++half) {
            const int e0 = half * 2, e1 = half * 2 + 1;
            float m = -1e9f;
#pragma unroll
            for (int nf = 0; nf < 8; ++nf)
                m = fmaxf(m, fmaxf(s[nf][e0], s[nf][e1]));
            m = fmaxf(m, __shfl_xor_sync(0xffffffffu, m, 1));
            m = fmaxf(m, __shfl_xor_sync(0xffffffffu, m, 2));
            vmax[half] = m;
        }
        // warp-uniform skip: if max didn't move anywhere in this warp,
        // corr == 1 exactly -> no o-rescale, no corr-exp.
        const bool noresc = __all_sync(0xffffffffu,
                                       vmax[0] <= s_m[0] && vmax[1] <= s_m[1]);
#pragma unroll
        for (int half = 0; half < 2; ++half) {
            const int e0 = half * 2, e1 = half * 2 + 1;
            const float mnew = noresc ? s_m[half] : fmaxf(s_m[half], vmax[half]);
            float rsum = 0.f;
#pragma unroll
            for (int nf = 0; nf < 8; ++nf) {
                // hybrid: half the exps on MUFU (idle pipe), half on FMA poly
                float p0 = mufu_exp2(s[nf][e0] - mnew);
                float p1 = fast_exp2(s[nf][e1] - mnew);
                s[nf][e0] = p0; s[nf][e1] = p1;
                rsum += p0 + p1;
            }
            rsum += __shfl_xor_sync(0xffffffffu, rsum, 1);
            rsum += __shfl_xor_sync(0xffffffffu, rsum, 2);
            if (noresc) {
                s_l[half] += rsum;
            } else {
                float corr = fast_exp2(s_m[half] - mnew);
                s_l[half] = s_l[half] * corr + rsum;
                s_m[half] = mnew;
#pragma unroll
                for (int nf = 0; nf < 8; ++nf) {
                    o[nf][e0] *= corr;
                    o[nf][e1] *= corr;
                }
            }
        }

        // ---- O += P @ V (single term; P rounded at pack) ----
#pragma unroll
        for (int kc = 0; kc < 4; ++kc) {
            uint32_t ph[4];
            ph[0] = pack_h2(s[2 * kc][0],     s[2 * kc][1]);
            ph[1] = pack_h2(s[2 * kc][2],     s[2 * kc][3]);
            ph[2] = pack_h2(s[2 * kc + 1][0], s[2 * kc + 1][1]);
            ph[3] = pack_h2(s[2 * kc + 1][2], s[2 * kc + 1][3]);
            uint32_t wh[4][4];
#pragma unroll
            for (int np = 0; np < 4; ++np) {
                int voe = vOffE + kc * 16 * FPITCH + np * 16;
                LDSM4T(wh[np][0], wh[np][1], wh[np][2], wh[np][3], vB + voe * 2);
            }
#pragma unroll
            for (int np = 0; np < 4; ++np) {
                MMA_F16(o[2 * np],     ph, wh[np][0], wh[np][1]);
                MMA_F16(o[2 * np + 1], ph, wh[np][2], wh[np][3]);
            }
        }
    }
    CP_WAIT(0);        // drain wrap-around produces (next call reuses stages)
    __syncthreads();   // smem reads done before caller refills Q region

    // ---- finalize: attn = o / l, stored as fp16 ----
    const float inv0 = 1.f / s_l[0];
    const float inv1 = 1.f / s_l[1];
#pragma unroll
    for (int nf = 0; nf < 8; ++nf) {
        int col = colbase + nf * 8 + ((lane & 3) << 1);
        size_t r0off = ((size_t)rg0 * B_DIM + b) * E_DIM + col;
        size_t r1off = ((size_t)(rg0 + 8) * B_DIM + b) * E_DIM + col;
        *(uint32_t*)(gA + r0off) = pack_h2(o[nf][0] * inv0, o[nf][1] * inv0);
        *(uint32_t*)(gA + r1off) = pack_h2(o[nf][2] * inv1, o[nf][3] * inv1);
    }
}

__global__ void __launch_bounds__(256, 2)
flash_mma_kernel(const float* __restrict__ Wo)
{
    extern __shared__ char dynsm[];
    const uint32_t smb = smem_u32(dynsm);

    const int tid  = threadIdx.x;

    // ---- side slice: convert Wo -> fp16 in flash's shadow ----
    if (blockIdx.y == 32) {
        const float4* src = (const float4*)Wo;
        __half* dst = gW + ((size_t)3 << 20);
        const int base = blockIdx.x * 256 + tid;      // 0..2047
#pragma unroll 4
        for (int i = base; i < 262144; i += 2048) {
            float4 v = src[i];
            *(uint2*)(dst + (size_t)i * 4) =
                make_uint2(pack_h2(v.x, v.y), pack_h2(v.z, v.w));
        }
        return;
    }

    const int lane = tid & 31;
    const int w    = tid >> 5;
    const int pair = blockIdx.x;          // 0..7
    const int head = blockIdx.y;          // 0..31
    const int b    = head >> 4;
    const int h    = head & 15;
    const int colbase = h * DH;

    const int qOffE = (w * 16 + (lane & 15)) * FPITCH + ((lane >> 4) & 1) * 8;
    const int kOffE = ((lane & 7) + ((lane >> 4) & 1) * 8) * FPITCH + ((lane >> 3) & 1) * 8;
    const int vOffE = ((lane & 7) + ((lane >> 3) & 1) * 8) * FPITCH + ((lane >> 4) & 1) * 8;

    // balanced pair: (pair) and (15 - pair) -> 34 kv-tiles per CTA, uniform
    flash_one(pair,      smb, b, colbase, tid, lane, w, qOffE, kOffE, vOffE);
    flash_one(15 - pair, smb, b, colbase, tid, lane, w, qOffE, kOffE, vOffE);
}

// ===========================================================================
// kernel_launch
// Inputs: query, Wq, bq, Wk, bk, Wv, bv, Wo, bo, attn_mask (ignored: causal)
// ===========================================================================
extern "C" void kernel_launch(void* const* d_in, const int* in_sizes, int n_in,
                              void* d_out, int out_size)
{
    const float* query = (const float*)d_in[0];
    const float* Wq    = (const float*)d_in[1];
    const float* bq    = (const float*)d_in[2];
    const float* Wk    = (const float*)d_in[3];
    const float* bk    = (const float*)d_in[4];
    const float* Wv    = (const float*)d_in[5];
    const float* bv    = (const float*)d_in[6];
    const float* Wo    = (const float*)d_in[7];
    const float* bo    = (const float*)d_in[8];
    float* out = (float*)d_out;

    cudaFuncSetAttribute(qkv_kernel, cudaFuncAttributeMaxDynamicSharedMemorySize, GSMEM_BYTES);
    cudaFuncSetAttribute(oproj_kernel, cudaFuncAttributeMaxDynamicSharedMemorySize, GSMEM_BYTES);
    cudaFuncSetAttribute(flash_mma_kernel, cudaFuncAttributeMaxDynamicSharedMemorySize, FSMEM_BYTES);

    // X, Wq, Wk, Wv -> fp16 (Wo converted inside the flash launch)
    convert_kernel<<<1792, 256>>>(query, Wq, Wk, Wv);

    // QKV projections (all 1-term) -> fp16 q,k,v
    qkv_kernel<<<dim3(E_DIM / 128, MROWS / 128, 3), 256, GSMEM_BYTES>>>(bq, bk, bv);

    // causal flash attention: 8 balanced q-tile pairs x 32 heads,
    // + y==32 slice converts Wo in the flash shadow
    flash_mma_kernel<<<dim3(8, B_DIM * H_DIM + 1), 256, FSMEM_BYTES>>>(Wo);

    // output projection -> f32 out
    oproj_kernel<<<dim3(E_DIM / 128, MROWS / 128), 256, GSMEM_BYTES>>>(bo, out);
}